// round 2
// baseline (speedup 1.0000x reference)
#include <cuda_runtime.h>

// Scratch: per-row layer-1 scalars for the 70 batch rows that actually matter.
// slots 0..63  : rows 64*i          (branch 3, W2 column 1)
// slots 64..69 : rows {0,682,1365,2048,2730,3413} (branch 4, W2 cols 65,69,67,65,69,67)
__device__ float g_s[70];

__constant__ int c_r4[6] = {0, 682, 1365, 2048, 2730, 3413};
__constant__ int c_c4[6] = {65, 69, 67, 65, 69, 67};

// ---------------------------------------------------------------------------
// Kernel A: 70 dot products of length 6400 against W1, + bias + relu.
// One block per needed batch row. float4 loads, warp-shuffle reduction.
// ---------------------------------------------------------------------------
__global__ void __launch_bounds__(256) dot_kernel(const float* __restrict__ inp,
                                                  const float* __restrict__ W1,
                                                  const float* __restrict__ b1) {
    __shared__ float warp_sums[8];
    int slot = blockIdx.x;
    int row = (slot < 64) ? (slot * 64) : c_r4[slot - 64];

    const float4* x = reinterpret_cast<const float4*>(inp + (size_t)row * 6400);
    const float4* w = reinterpret_cast<const float4*>(W1);

    float sum = 0.f;
    // 6400 floats = 1600 float4 per row
    #pragma unroll 2
    for (int i = threadIdx.x; i < 1600; i += 256) {
        float4 a = x[i];
        float4 b = w[i];
        sum = fmaf(a.x, b.x, sum);
        sum = fmaf(a.y, b.y, sum);
        sum = fmaf(a.z, b.z, sum);
        sum = fmaf(a.w, b.w, sum);
    }
    // warp reduce
    #pragma unroll
    for (int off = 16; off > 0; off >>= 1)
        sum += __shfl_down_sync(0xffffffffu, sum, off);

    int lane = threadIdx.x & 31;
    int wid  = threadIdx.x >> 5;
    if (lane == 0) warp_sums[wid] = sum;
    __syncthreads();
    if (wid == 0) {
        sum = (lane < 8) ? warp_sums[lane] : 0.f;
        #pragma unroll
        for (int off = 4; off > 0; off >>= 1)
            sum += __shfl_down_sync(0xffffffffu, sum, off);
        if (lane == 0) g_s[slot] = fmaxf(sum + b1[0], 0.f);
    }
}

// ---------------------------------------------------------------------------
// Kernel B: evaluate the tiny hyper-MLPs (in shared, once per block) and
// stream the 412,742-float output:
//   [0, 409600)        : sel3(64x80) tiled 80 times  -> value = f(t % 5120)
//   [409600, 409664)   : zeros
//   [409664, 412742)   : sel4 (6 x 513)
// ---------------------------------------------------------------------------
#define SEG3_END   409600
#define BIAS_END   409664
#define OUT_TOTAL  412742

__global__ void __launch_bounds__(256) out_kernel(const float* __restrict__ W2,
                                                  const float* __restrict__ b2,
                                                  const float* __restrict__ W3a,
                                                  const float* __restrict__ b3a,
                                                  const float* __restrict__ W3b,
                                                  const float* __restrict__ b3b,
                                                  const float* __restrict__ W4a,
                                                  const float* __restrict__ b4a,
                                                  const float* __restrict__ W4b,
                                                  const float* __restrict__ b4b,
                                                  float* __restrict__ out) {
    __shared__ float sh_a3[64];
    __shared__ float sh_a4[6];
    __shared__ float sh_w3b[80];
    __shared__ float sh_b3b[80];

    int tid = threadIdx.x;
    if (tid < 64) {
        // layer2 (col 1) then W3a chain, relu each stage
        float x1 = fmaxf(fmaf(g_s[tid], W2[1], b2[1]), 0.f);
        sh_a3[tid] = fmaxf(fmaf(x1, W3a[0], b3a[0]), 0.f);
    } else if (tid < 70) {
        int j = tid - 64;
        int c = c_c4[j];
        float x1 = fmaxf(fmaf(g_s[tid], W2[c], b2[c]), 0.f);
        sh_a4[j] = fmaxf(fmaf(x1, W4a[0], b4a[0]), 0.f);
    } else if (tid >= 128 && tid < 208) {
        int k = tid - 128;
        sh_w3b[k] = W3b[k];
        sh_b3b[k] = b3b[k];
    }
    __syncthreads();

    long base = ((long)blockIdx.x * 256 + tid) * 4;
    if (base >= OUT_TOTAL) return;

    if (base + 4 <= SEG3_END) {
        // Fast path: 4 consecutive outputs, same i (80 % 4 == 0, idx % 4 == 0)
        int idx = (int)(base % 5120);
        int i = idx / 80;
        int k = idx % 80;
        float a = sh_a3[i];
        float4 v;
        v.x = fmaxf(fmaf(a, sh_w3b[k    ], sh_b3b[k    ]), 0.f);
        v.y = fmaxf(fmaf(a, sh_w3b[k + 1], sh_b3b[k + 1]), 0.f);
        v.z = fmaxf(fmaf(a, sh_w3b[k + 2], sh_b3b[k + 2]), 0.f);
        v.w = fmaxf(fmaf(a, sh_w3b[k + 3], sh_b3b[k + 3]), 0.f);
        *reinterpret_cast<float4*>(out + base) = v;
    } else {
        // Tail: bias zeros + sel4 region, element-wise with bounds checks
        #pragma unroll
        for (int e = 0; e < 4; e++) {
            long t = base + e;
            if (t >= OUT_TOTAL) break;
            float v;
            if (t < SEG3_END) {
                int idx = (int)(t % 5120);
                v = fmaxf(fmaf(sh_a3[idx / 80], sh_w3b[idx % 80], sh_b3b[idx % 80]), 0.f);
            } else if (t < BIAS_END) {
                v = 0.f;
            } else {
                long u = t - BIAS_END;
                int j = (int)(u / 513);
                int k = (int)(u % 513);
                v = fmaxf(fmaf(sh_a4[j], __ldg(W4b + k), __ldg(b4b + k)), 0.f);
            }
            out[t] = v;
        }
    }
}

extern "C" void kernel_launch(void* const* d_in, const int* in_sizes, int n_in,
                              void* d_out, int out_size) {
    const float* inputs = (const float*)d_in[0];
    const float* W1  = (const float*)d_in[1];
    const float* b1  = (const float*)d_in[2];
    const float* W2  = (const float*)d_in[3];
    const float* b2  = (const float*)d_in[4];
    const float* W3a = (const float*)d_in[5];
    const float* b3a = (const float*)d_in[6];
    const float* W3b = (const float*)d_in[7];
    const float* b3b = (const float*)d_in[8];
    const float* W4a = (const float*)d_in[9];
    const float* b4a = (const float*)d_in[10];
    const float* W4b = (const float*)d_in[11];
    const float* b4b = (const float*)d_in[12];
    float* out = (float*)d_out;

    dot_kernel<<<70, 256>>>(inputs, W1, b1);

    // ceil(412742 / 4) = 103186 threads -> ceil(103186 / 256) = 404 blocks
    out_kernel<<<404, 256>>>(W2, b2, W3a, b3a, W3b, b3b, W4a, b4a, W4b, b4b, out);
}

// round 5
// speedup vs baseline: 1.3077x; 1.3077x over previous
#include <cuda_runtime.h>

// Rows / W2-columns that actually matter (derived from the reshape-select in the
// reference; validated by the passing R2 kernel):
//   branch3: slot i<64  -> batch row 64*i,      W2 column 1
//   branch4: slot 64+j  -> rows {0,682,1365,2048,2730,3413}, cols {65,69,67,65,69,67}
__constant__ int c_r4[6] = {0, 682, 1365, 2048, 2730, 3413};
__constant__ int c_c4[6] = {65, 69, 67, 65, 69, 67};

#define SEG3_END   409600
#define BIAS_END   409664

// ---------------------------------------------------------------------------
// Single fused kernel: 70 blocks, each fully owns one dot product and all of
// the output elements that depend on it. No inter-block dependencies.
// ---------------------------------------------------------------------------
__global__ void __launch_bounds__(512) fused_kernel(const float* __restrict__ inp,
                                                    const float* __restrict__ W1,
                                                    const float* __restrict__ b1,
                                                    const float* __restrict__ W2,
                                                    const float* __restrict__ b2,
                                                    const float* __restrict__ W3a,
                                                    const float* __restrict__ b3a,
                                                    const float* __restrict__ W3b,
                                                    const float* __restrict__ b3b,
                                                    const float* __restrict__ W4a,
                                                    const float* __restrict__ b4a,
                                                    const float* __restrict__ W4b,
                                                    const float* __restrict__ b4b,
                                                    float* __restrict__ out) {
    __shared__ float warp_sums[16];
    __shared__ float sh_v[80];   // branch3: relu(a3*W3b[k]+b3b[k]) per k
    __shared__ float sh_a;       // the per-block hidden scalar

    int slot = blockIdx.x;
    int tid  = threadIdx.x;
    int lane = tid & 31;
    int wid  = tid >> 5;

    int row = (slot < 64) ? (slot * 64) : c_r4[slot - 64];

    // --- Phase 1: dot(inp[row], W1) over 6400 floats (1600 float4) ---
    const float4* x = reinterpret_cast<const float4*>(inp + (size_t)row * 6400);
    const float4* w = reinterpret_cast<const float4*>(W1);

    float sum = 0.f;
    #pragma unroll 4
    for (int i = tid; i < 1600; i += 512) {
        float4 a = x[i];
        float4 b = w[i];
        sum = fmaf(a.x, b.x, sum);
        sum = fmaf(a.y, b.y, sum);
        sum = fmaf(a.z, b.z, sum);
        sum = fmaf(a.w, b.w, sum);
    }
    #pragma unroll
    for (int off = 16; off > 0; off >>= 1)
        sum += __shfl_down_sync(0xffffffffu, sum, off);
    if (lane == 0) warp_sums[wid] = sum;
    __syncthreads();
    if (wid == 0) {
        sum = (lane < 16) ? warp_sums[lane] : 0.f;
        #pragma unroll
        for (int off = 8; off > 0; off >>= 1)
            sum += __shfl_down_sync(0xffffffffu, sum, off);
        if (lane == 0) {
            float s = fmaxf(sum + __ldg(b1), 0.f);
            if (slot < 64) {
                float x1 = fmaxf(fmaf(s, __ldg(W2 + 1), __ldg(b2 + 1)), 0.f);
                sh_a = fmaxf(fmaf(x1, __ldg(W3a), __ldg(b3a)), 0.f);
            } else {
                int c = c_c4[slot - 64];
                float x1 = fmaxf(fmaf(s, __ldg(W2 + c), __ldg(b2 + c)), 0.f);
                sh_a = fmaxf(fmaf(x1, __ldg(W4a), __ldg(b4a)), 0.f);
            }
        }
    }
    __syncthreads();
    float a = sh_a;

    // --- Phase 2: stream this block's output slice ---
    if (slot < 64) {
        // Compute the 80 final values once, then replicate to all 80 tiles.
        if (tid < 80)
            sh_v[tid] = fmaxf(fmaf(a, __ldg(W3b + tid), __ldg(b3b + tid)), 0.f);
        __syncthreads();

        float* base = out + slot * 80;
        // 80 tiles x 20 float4 each = 1600 float4 stores
        #pragma unroll 4
        for (int m = tid; m < 1600; m += 512) {
            int p  = m / 20;           // tile index (0..79)
            int k4 = (m - p * 20) * 4; // element within the 80-float group
            float4 v = *reinterpret_cast<const float4*>(sh_v + k4);
            *reinterpret_cast<float4*>(base + p * 5120 + k4) = v;
        }
    } else {
        int j = slot - 64;
        float* base = out + BIAS_END + j * 513;
        for (int k = tid; k < 513; k += 512)
            base[k] = fmaxf(fmaf(a, __ldg(W4b + k), __ldg(b4b + k)), 0.f);
        if (j == 0 && tid < 64)
            out[SEG3_END + tid] = 0.f;
    }
}

extern "C" void kernel_launch(void* const* d_in, const int* in_sizes, int n_in,
                              void* d_out, int out_size) {
    const float* inputs = (const float*)d_in[0];
    const float* W1  = (const float*)d_in[1];
    const float* b1  = (const float*)d_in[2];
    const float* W2  = (const float*)d_in[3];
    const float* b2  = (const float*)d_in[4];
    const float* W3a = (const float*)d_in[5];
    const float* b3a = (const float*)d_in[6];
    const float* W3b = (const float*)d_in[7];
    const float* b3b = (const float*)d_in[8];
    const float* W4a = (const float*)d_in[9];
    const float* b4a = (const float*)d_in[10];
    const float* W4b = (const float*)d_in[11];
    const float* b4b = (const float*)d_in[12];
    float* out = (float*)d_out;

    fused_kernel<<<70, 512>>>(inputs, W1, b1, W2, b2, W3a, b3a, W3b, b3b,
                              W4a, b4a, W4b, b4b, out);
}